// round 10
// baseline (speedup 1.0000x reference)
#include <cuda_runtime.h>
#include <cuda_fp16.h>
#include <math.h>
#include <stdint.h>

// Problem constants
#define BATCH 4
#define TSZ   1024
#define DIM   1024
#define NHEAD 16
#define HDIM  64
#define C3    (3 * DIM)

// Scratch (allocation-free: __device__ globals) — fp16 pipeline
__device__ __half g_xh[BATCH * TSZ * DIM];
__device__ __half g_wqkvh[C3 * DIM];
__device__ __half g_wprojh[DIM * DIM];
__device__ __half g_qkvh[BATCH * TSZ * C3];   // [B,T,3C]
__device__ __half g_atth[BATCH * TSZ * DIM];  // [B,T,C]

// ---------------------------------------------------------------------------
// helpers
// ---------------------------------------------------------------------------
__device__ __forceinline__ void mma_f16(float c[4], const uint32_t a[4],
                                        uint32_t b0, uint32_t b1) {
    asm volatile(
        "mma.sync.aligned.m16n8k16.row.col.f32.f16.f16.f32 "
        "{%0,%1,%2,%3}, {%4,%5,%6,%7}, {%8,%9}, {%0,%1,%2,%3};"
        : "+f"(c[0]), "+f"(c[1]), "+f"(c[2]), "+f"(c[3])
        : "r"(a[0]), "r"(a[1]), "r"(a[2]), "r"(a[3]), "r"(b0), "r"(b1));
}

__device__ __forceinline__ void ldsm_x4(uint32_t& r0, uint32_t& r1, uint32_t& r2,
                                        uint32_t& r3, uint32_t saddr) {
    asm volatile(
        "ldmatrix.sync.aligned.m8n8.x4.shared.b16 {%0,%1,%2,%3}, [%4];"
        : "=r"(r0), "=r"(r1), "=r"(r2), "=r"(r3)
        : "r"(saddr));
}

__device__ __forceinline__ void ldsm_x4_trans(uint32_t& r0, uint32_t& r1,
                                              uint32_t& r2, uint32_t& r3,
                                              uint32_t saddr) {
    asm volatile(
        "ldmatrix.sync.aligned.m8n8.x4.trans.shared.b16 {%0,%1,%2,%3}, [%4];"
        : "=r"(r0), "=r"(r1), "=r"(r2), "=r"(r3)
        : "r"(saddr));
}

__device__ __forceinline__ uint4 f8_to_h8(float4 a, float4 b) {
    __half2 h0 = __floats2half2_rn(a.x, a.y);
    __half2 h1 = __floats2half2_rn(a.z, a.w);
    __half2 h2 = __floats2half2_rn(b.x, b.y);
    __half2 h3 = __floats2half2_rn(b.z, b.w);
    uint4 u;
    u.x = *(uint32_t*)&h0; u.y = *(uint32_t*)&h1;
    u.z = *(uint32_t*)&h2; u.w = *(uint32_t*)&h3;
    return u;
}

#define CP_ASYNC16(dst, src) \
    asm volatile("cp.async.cg.shared.global [%0], [%1], 16;" :: "r"(dst), "l"(src))
#define CP_COMMIT() asm volatile("cp.async.commit_group;")
#define CP_WAIT0()  asm volatile("cp.async.wait_group 0;")
#define CP_WAIT1()  asm volatile("cp.async.wait_group 1;")
#define CP_WAIT2()  asm volatile("cp.async.wait_group 2;")

// fp16 m16n8k16 fragment lane->address components (offsets in halves):
#define A16_ROW(lane) ((lane) & 15)
#define A16_KOF(lane) (((lane) >> 4) * 8)
#define B16_ROW(lane) (((lane) & 7) + ((lane) >> 4) * 8)
#define B16_KOF(lane) ((((lane) >> 3) & 1) * 8)

// ---------------------------------------------------------------------------
// fused fp32 -> fp16 conversion of all three inputs (8 elts/thread)
// sizes divisible by 2048 -> whole block maps to one region, no divergence
// ---------------------------------------------------------------------------
#define N_X  (BATCH * TSZ * DIM)   // 4194304
#define N_WQ (C3 * DIM)            // 3145728
#define N_WP (DIM * DIM)           // 1048576

__global__ __launch_bounds__(256)
void cvt3_f32_f16(const float* __restrict__ x, const float* __restrict__ wq,
                  const float* __restrict__ wp, __half* __restrict__ xh,
                  __half* __restrict__ wqh, __half* __restrict__ wph) {
    long i = ((long)blockIdx.x * 256 + threadIdx.x) * 8;
    const float* src;
    __half* dst;
    if (i < N_X) {
        src = x + i; dst = xh + i;
    } else if (i < (long)N_X + N_WQ) {
        src = wq + (i - N_X); dst = wqh + (i - N_X);
    } else {
        src = wp + (i - N_X - N_WQ); dst = wph + (i - N_X - N_WQ);
    }
    float4 a = *(const float4*)(src);
    float4 b = *(const float4*)(src + 4);
    *(uint4*)(dst) = f8_to_h8(a, b);
}

// ---------------------------------------------------------------------------
// FP16 GEMM (NT): C[m,n] = sum_k A[m,k]*B[n,k] (+bias[n])
// Block 128x256, BK=32, 512 thr = 16 warps (4x4), warp tile 32x64.
// 4-stage cp.async pipeline, ONE barrier per k-tile, stride 40 halves.
// ---------------------------------------------------------------------------
#define BK 32
#define ASTR 40
#define SA_H (128 * ASTR)
#define SB_H (256 * ASTR)
#define STAGE_H (SA_H + SB_H)
#define GSTAGES 4
#define GEMM_SMEM (GSTAGES * STAGE_H * 2)

template <bool BIAS, bool OUT_HALF>
__global__ __launch_bounds__(512, 1)
void f16_gemm_nt(const __half* __restrict__ A, const __half* __restrict__ B,
                 const float* __restrict__ bias, void* __restrict__ Cv,
                 int M, int N, int K) {
    extern __shared__ __half gsm[];

    const int tid  = threadIdx.x;
    const int lane = tid & 31;
    const int warp = tid >> 5;         // 0..15
    const int g = lane >> 2;
    const int t = lane & 3;
    const int wm = (warp >> 2) * 32;
    const int wn = (warp & 3) * 64;
    const int bm = blockIdx.y * 128;
    const int bn = blockIdx.x * 256;

    // staging: thread -> (row = tid>>2, chunk = (tid&3)*8 halves)
    const int srow = tid >> 2;         // 0..127
    const int sch  = (tid & 3) * 8;    // 0,8,16,24

    const __half* Ap  = A + (size_t)(bm + srow) * K + sch;
    const __half* Bp0 = B + (size_t)(bn + srow) * K + sch;
    const __half* Bp1 = B + (size_t)(bn + 128 + srow) * K + sch;

    const uint32_t smem0 = (uint32_t)__cvta_generic_to_shared(gsm);
    const uint32_t dA  = 2u * (srow * ASTR + sch);
    const uint32_t dB1 = 2u * ((128 + srow) * ASTR + sch);

    const int ar = A16_ROW(lane), ak = A16_KOF(lane);
    const int br = B16_ROW(lane), bk = B16_KOF(lane);

    float acc[2][8][4];
#pragma unroll
    for (int i = 0; i < 2; i++)
#pragma unroll
        for (int j = 0; j < 8; j++)
#pragma unroll
            for (int q = 0; q < 4; q++) acc[i][j][q] = 0.f;

#define G_STAGE(slot, kt)                                                      \
    do {                                                                       \
        const uint32_t so = smem0 + 2u * (uint32_t)(slot) * STAGE_H;           \
        CP_ASYNC16(so + dA, Ap + (kt) * BK);                                   \
        CP_ASYNC16(so + 2u * SA_H + dA, Bp0 + (kt) * BK);                      \
        CP_ASYNC16(so + 2u * SA_H + dB1, Bp1 + (kt) * BK);                     \
        CP_COMMIT();                                                           \
    } while (0)

    const int NT = K / BK;
    G_STAGE(0, 0);
    G_STAGE(1, 1);
    G_STAGE(2, 2);

    for (int kt = 0; kt < NT; kt++) {
        CP_WAIT2();          // group for tile kt complete (3 groups pending)
        __syncthreads();     // visibility + slot (kt-1)%4 consumers done
        if (kt + 3 < NT) G_STAGE((kt + 3) & 3, kt + 3);
        else CP_COMMIT();    // empty group keeps pending-count invariant

        const uint32_t aA = smem0 + 2u * (uint32_t)(kt & 3) * STAGE_H;
        const uint32_t aB = aA + 2u * SA_H;
#pragma unroll
        for (int kk = 0; kk < 2; kk++) {
            uint32_t af[2][4];
#pragma unroll
            for (int mt = 0; mt < 2; mt++)
                ldsm_x4(af[mt][0], af[mt][1], af[mt][2], af[mt][3],
                        aA + 2u * ((wm + mt * 16 + ar) * ASTR + kk * 16 + ak));
#pragma unroll
            for (int p = 0; p < 4; p++) {
                uint32_t b0, b1, b2, b3;
                ldsm_x4(b0, b1, b2, b3,
                        aB + 2u * ((wn + p * 16 + br) * ASTR + kk * 16 + bk));
#pragma unroll
                for (int mt = 0; mt < 2; mt++) {
                    mma_f16(acc[mt][2 * p],     af[mt], b0, b1);
                    mma_f16(acc[mt][2 * p + 1], af[mt], b2, b3);
                }
            }
        }
    }

    // Epilogue
#pragma unroll
    for (int mt = 0; mt < 2; mt++) {
#pragma unroll
        for (int nt = 0; nt < 8; nt++) {
            const float* a4 = acc[mt][nt];
            const int row = bm + wm + mt * 16 + g;
            const int col = bn + wn + nt * 8 + 2 * t;
            if (OUT_HALF) {
                __half* C = (__half*)Cv;
                __half2 v0 = __floats2half2_rn(a4[0], a4[1]);
                __half2 v1 = __floats2half2_rn(a4[2], a4[3]);
                *(uint32_t*)&C[(size_t)row * N + col] = *(uint32_t*)&v0;
                *(uint32_t*)&C[(size_t)(row + 8) * N + col] = *(uint32_t*)&v1;
            } else {
                float* C = (float*)Cv;
                float bx = 0.f, by = 0.f;
                if (BIAS) { bx = bias[col]; by = bias[col + 1]; }
                float2 v0 = {a4[0] + bx, a4[1] + by};
                float2 v1 = {a4[2] + bx, a4[3] + by};
                *(float2*)(C + (size_t)row * N + col) = v0;
                *(float2*)(C + (size_t)(row + 8) * N + col) = v1;
            }
        }
    }
}

// ---------------------------------------------------------------------------
// FP16 flash attention, 3-stage cp.async KV pipeline, ONE barrier per tile.
// 256 threads = 8 warps, 128 q-rows, 16 kv-tiles of 64.
// smem: 3 x {K,V} stages [64][72], then sQP [128][72] (Q staging, then P).
// ---------------------------------------------------------------------------
#define FSTR 72
#define KV_H (64 * FSTR)          // halves per K (or V) tile
#define FSTAGE_H (2 * KV_H)       // K+V per stage
#define FLASH_HALVES (3 * FSTAGE_H + 128 * FSTR)
#define FLASH_SMEM   (FLASH_HALVES * 2)

__global__ __launch_bounds__(256)
void flash_f16(const __half* __restrict__ qkv, __half* __restrict__ att) {
    extern __shared__ __half fsm[];

    const int tid  = threadIdx.x;
    const int lane = tid & 31;
    const int warp = tid >> 5;
    const int g = lane >> 2;
    const int t = lane & 3;
    const int bh = blockIdx.y;
    const int b = bh >> 4;
    const int h = bh & 15;
    const int q0 = blockIdx.x * 128;
    const size_t base = (size_t)b * TSZ * C3;
    const int hoff = h * HDIM;
    const float qscale = 0.125f * 1.44269504088896340736f;  // scale * log2(e)

    const uint32_t smem0 = (uint32_t)__cvta_generic_to_shared(fsm);
    const uint32_t sQPb = smem0 + 2u * 3 * FSTAGE_H;
    const uint32_t sPwb = sQPb + 2u * (warp * 16 * FSTR);
    __half* sQP = fsm + 3 * FSTAGE_H;

    const int ar = A16_ROW(lane), ak = A16_KOF(lane);
    const int br = B16_ROW(lane), bk = B16_KOF(lane);
    const int vj = (lane & 7) + ((lane >> 3) & 1) * 8;
    const int vd = (lane >> 4) * 8;

    // Q staging (group 1): 128 rows x 8 chunks = 1024 cp, 4 per thread
#pragma unroll
    for (int it = 0; it < 4; it++) {
        const int i = tid + it * 256;
        const int r = i >> 3, c8 = (i & 7) * 8;
        CP_ASYNC16(sQPb + 2u * (r * FSTR + c8),
                   qkv + base + (size_t)(q0 + r) * C3 + hoff + c8);
    }
    CP_COMMIT();

#define KV_STAGE(slot, kt)                                                     \
    do {                                                                       \
        const uint32_t so = smem0 + 2u * (uint32_t)(slot) * FSTAGE_H;          \
        const __half* srcb = qkv + base + (size_t)((kt) * 64) * C3 + hoff;     \
        _Pragma("unroll")                                                      \
        for (int it = 0; it < 2; it++) {                                       \
            const int i = tid + it * 256;                                      \
            const int r = i >> 3, c8 = (i & 7) * 8;                            \
            CP_ASYNC16(so + 2u * (r * FSTR + c8),                              \
                       srcb + (size_t)r * C3 + DIM + c8);                      \
            CP_ASYNC16(so + 2u * (KV_H + r * FSTR + c8),                       \
                       srcb + (size_t)r * C3 + 2 * DIM + c8);                  \
        }                                                                      \
        CP_COMMIT();                                                           \
    } while (0)

    KV_STAGE(0, 0);
    KV_STAGE(1, 1);

    // Wait for Q (2 KV groups may stay pending), load Q fragments
    CP_WAIT2();
    __syncthreads();
    uint32_t aq[4][4];
#pragma unroll
    for (int kk = 0; kk < 4; kk++)
        ldsm_x4(aq[kk][0], aq[kk][1], aq[kk][2], aq[kk][3],
                sQPb + 2u * ((warp * 16 + ar) * FSTR + kk * 16 + ak));

    float accO[8][4];
#pragma unroll
    for (int i = 0; i < 8; i++)
#pragma unroll
        for (int j = 0; j < 4; j++) accO[i][j] = 0.f;
    float m0 = -INFINITY, m1 = -INFINITY, l0 = 0.f, l1 = 0.f;

    for (int kt = 0; kt < 16; kt++) {
        CP_WAIT1();          // KV tile kt complete (2 KV groups pending)
        __syncthreads();     // visibility + slot (kt-1)%3 consumers done
        if (kt + 2 < 16) KV_STAGE((kt + 2) % 3, kt + 2);
        else CP_COMMIT();

        const uint32_t sKc = smem0 + 2u * (uint32_t)(kt % 3) * FSTAGE_H;
        const uint32_t sVc = sKc + 2u * KV_H;

        // S = Q * K^T
        float accS[8][4];
#pragma unroll
        for (int i = 0; i < 8; i++)
#pragma unroll
            for (int j = 0; j < 4; j++) accS[i][j] = 0.f;
#pragma unroll
        for (int kk = 0; kk < 4; kk++) {
#pragma unroll
            for (int p = 0; p < 4; p++) {
                uint32_t b0, b1, b2, b3;
                ldsm_x4(b0, b1, b2, b3,
                        sKc + 2u * ((p * 16 + br) * FSTR + kk * 16 + bk));
                mma_f16(accS[2 * p],     aq[kk], b0, b1);
                mma_f16(accS[2 * p + 1], aq[kk], b2, b3);
            }
        }
#pragma unroll
        for (int nt = 0; nt < 8; nt++) {
            accS[nt][0] *= qscale; accS[nt][1] *= qscale;
            accS[nt][2] *= qscale; accS[nt][3] *= qscale;
        }

        // Online softmax (rows g, g+8), base-2 domain
        float r0 = -INFINITY, r1 = -INFINITY;
#pragma unroll
        for (int nt = 0; nt < 8; nt++) {
            r0 = fmaxf(r0, fmaxf(accS[nt][0], accS[nt][1]));
            r1 = fmaxf(r1, fmaxf(accS[nt][2], accS[nt][3]));
        }
        r0 = fmaxf(r0, __shfl_xor_sync(0xffffffffu, r0, 1));
        r0 = fmaxf(r0, __shfl_xor_sync(0xffffffffu, r0, 2));
        r1 = fmaxf(r1, __shfl_xor_sync(0xffffffffu, r1, 1));
        r1 = fmaxf(r1, __shfl_xor_sync(0xffffffffu, r1, 2));
        const float mn0 = fmaxf(m0, r0);
        const float mn1 = fmaxf(m1, r1);
        const float al0 = exp2f(m0 - mn0);
        const float al1 = exp2f(m1 - mn1);
        float rs0 = 0.f, rs1 = 0.f;
        __half* sPw = sQP + warp * 16 * FSTR;
#pragma unroll
        for (int nt = 0; nt < 8; nt++) {
            __half2 h01 = __floats2half2_rn(exp2f(accS[nt][0] - mn0),
                                            exp2f(accS[nt][1] - mn0));
            __half2 h23 = __floats2half2_rn(exp2f(accS[nt][2] - mn1),
                                            exp2f(accS[nt][3] - mn1));
            float2 f01 = __half22float2(h01);
            float2 f23 = __half22float2(h23);
            rs0 += f01.x + f01.y;
            rs1 += f23.x + f23.y;
            *(uint32_t*)&sPw[g * FSTR + nt * 8 + 2 * t]       = *(uint32_t*)&h01;
            *(uint32_t*)&sPw[(g + 8) * FSTR + nt * 8 + 2 * t] = *(uint32_t*)&h23;
        }
        rs0 += __shfl_xor_sync(0xffffffffu, rs0, 1);
        rs0 += __shfl_xor_sync(0xffffffffu, rs0, 2);
        rs1 += __shfl_xor_sync(0xffffffffu, rs1, 1);
        rs1 += __shfl_xor_sync(0xffffffffu, rs1, 2);
        l0 = l0 * al0 + rs0;
        l1 = l1 * al1 + rs1;
        m0 = mn0; m1 = mn1;
#pragma unroll
        for (int nt = 0; nt < 8; nt++) {
            accO[nt][0] *= al0; accO[nt][1] *= al0;
            accO[nt][2] *= al1; accO[nt][3] *= al1;
        }
        __syncwarp();

        // O += P V (P: A-frag; V: B-frag via ldmatrix.trans)
#pragma unroll
        for (int kk = 0; kk < 4; kk++) {
            uint32_t ap[4];
            ldsm_x4(ap[0], ap[1], ap[2], ap[3],
                    sPwb + 2u * (ar * FSTR + kk * 16 + ak));
#pragma unroll
            for (int p = 0; p < 4; p++) {
                uint32_t v0, v1, v2, v3;
                ldsm_x4_trans(v0, v1, v2, v3,
                              sVc + 2u * ((kk * 16 + vj) * FSTR + p * 16 + vd));
                mma_f16(accO[2 * p],     ap, v0, v1);
                mma_f16(accO[2 * p + 1], ap, v2, v3);
            }
        }
    }

    // Epilogue: normalize, write fp16 att [B,T,C]
    const float inv0 = 1.f / l0;
    const float inv1 = 1.f / l1;
    const int r0w = q0 + warp * 16 + g;
    __half* o0 = att + (size_t)b * TSZ * DIM + (size_t)r0w * DIM + hoff;
    __half* o1 = o0 + (size_t)8 * DIM;
#pragma unroll
    for (int nt = 0; nt < 8; nt++) {
        __half2 v0 = __floats2half2_rn(accO[nt][0] * inv0, accO[nt][1] * inv0);
        __half2 v1 = __floats2half2_rn(accO[nt][2] * inv1, accO[nt][3] * inv1);
        *(uint32_t*)&o0[nt * 8 + 2 * t] = *(uint32_t*)&v0;
        *(uint32_t*)&o1[nt * 8 + 2 * t] = *(uint32_t*)&v1;
    }
}

// ---------------------------------------------------------------------------
extern "C" void kernel_launch(void* const* d_in, const int* in_sizes, int n_in,
                              void* d_out, int out_size) {
    const float* x     = (const float*)d_in[0];  // [4,1024,1024]
    const float* Wqkv  = (const float*)d_in[1];  // [3072,1024]
    const float* Wproj = (const float*)d_in[2];  // [1024,1024]
    const float* bproj = (const float*)d_in[3];  // [1024]
    float* out = (float*)d_out;                  // [4,1024,1024]

    __half *xh, *wqkvh, *wprojh, *qkvh, *atth;
    cudaGetSymbolAddress((void**)&xh, g_xh);
    cudaGetSymbolAddress((void**)&wqkvh, g_wqkvh);
    cudaGetSymbolAddress((void**)&wprojh, g_wprojh);
    cudaGetSymbolAddress((void**)&qkvh, g_qkvh);
    cudaGetSymbolAddress((void**)&atth, g_atth);

    cudaFuncSetAttribute(f16_gemm_nt<false, true>,
                         cudaFuncAttributeMaxDynamicSharedMemorySize, GEMM_SMEM);
    cudaFuncSetAttribute(f16_gemm_nt<true, false>,
                         cudaFuncAttributeMaxDynamicSharedMemorySize, GEMM_SMEM);
    cudaFuncSetAttribute(flash_f16,
                         cudaFuncAttributeMaxDynamicSharedMemorySize, FLASH_SMEM);

    // 0) fused fp32 -> fp16 conversion (x, Wqkv, Wproj)
    cvt3_f32_f16<<<(N_X + N_WQ + N_WP) / 2048, 256>>>(x, Wqkv, Wproj,
                                                      xh, wqkvh, wprojh);

    // 1) QKV projection -> fp16: [4096,1024] x [3072,1024]^T -> [4096,3072]
    f16_gemm_nt<false, true><<<dim3(C3 / 256, (BATCH * TSZ) / 128), 512,
                               GEMM_SMEM>>>(xh, wqkvh, nullptr, qkvh,
                                            BATCH * TSZ, C3, DIM);

    // 2) Attention (fp16 in/out)
    flash_f16<<<dim3(TSZ / 128, BATCH * NHEAD), 256, FLASH_SMEM>>>(qkvh, atth);

    // 3) Output projection + bias -> fp32 out
    f16_gemm_nt<true, false><<<dim3(DIM / 256, (BATCH * TSZ) / 128), 512,
                               GEMM_SMEM>>>(atth, wprojh, bproj, out,
                                            BATCH * TSZ, DIM, DIM);
}

// round 11
// speedup vs baseline: 1.4090x; 1.4090x over previous
#include <cuda_runtime.h>
#include <cuda_fp16.h>
#include <math.h>
#include <stdint.h>

// Problem constants
#define BATCH 4
#define TSZ   1024
#define DIM   1024
#define NHEAD 16
#define HDIM  64
#define C3    (3 * DIM)

// Scratch (allocation-free: __device__ globals) — fp16 pipeline
__device__ __half g_xh[BATCH * TSZ * DIM];
__device__ __half g_wqkvh[C3 * DIM];
__device__ __half g_wprojh[DIM * DIM];
__device__ __half g_qkvh[BATCH * TSZ * C3];   // [B,T,3C]
__device__ __half g_atth[BATCH * TSZ * DIM];  // [B,T,C]

// ---------------------------------------------------------------------------
// helpers
// ---------------------------------------------------------------------------
__device__ __forceinline__ void mma_f16(float c[4], const uint32_t a[4],
                                        uint32_t b0, uint32_t b1) {
    asm volatile(
        "mma.sync.aligned.m16n8k16.row.col.f32.f16.f16.f32 "
        "{%0,%1,%2,%3}, {%4,%5,%6,%7}, {%8,%9}, {%0,%1,%2,%3};"
        : "+f"(c[0]), "+f"(c[1]), "+f"(c[2]), "+f"(c[3])
        : "r"(a[0]), "r"(a[1]), "r"(a[2]), "r"(a[3]), "r"(b0), "r"(b1));
}

__device__ __forceinline__ void ldsm_x4(uint32_t& r0, uint32_t& r1, uint32_t& r2,
                                        uint32_t& r3, uint32_t saddr) {
    asm volatile(
        "ldmatrix.sync.aligned.m8n8.x4.shared.b16 {%0,%1,%2,%3}, [%4];"
        : "=r"(r0), "=r"(r1), "=r"(r2), "=r"(r3)
        : "r"(saddr));
}

__device__ __forceinline__ void ldsm_x4_trans(uint32_t& r0, uint32_t& r1,
                                              uint32_t& r2, uint32_t& r3,
                                              uint32_t saddr) {
    asm volatile(
        "ldmatrix.sync.aligned.m8n8.x4.trans.shared.b16 {%0,%1,%2,%3}, [%4];"
        : "=r"(r0), "=r"(r1), "=r"(r2), "=r"(r3)
        : "r"(saddr));
}

__device__ __forceinline__ uint4 f8_to_h8(float4 a, float4 b) {
    __half2 h0 = __floats2half2_rn(a.x, a.y);
    __half2 h1 = __floats2half2_rn(a.z, a.w);
    __half2 h2 = __floats2half2_rn(b.x, b.y);
    __half2 h3 = __floats2half2_rn(b.z, b.w);
    uint4 u;
    u.x = *(uint32_t*)&h0; u.y = *(uint32_t*)&h1;
    u.z = *(uint32_t*)&h2; u.w = *(uint32_t*)&h3;
    return u;
}

#define CP_ASYNC16(dst, src) \
    asm volatile("cp.async.cg.shared.global [%0], [%1], 16;" :: "r"(dst), "l"(src))
#define CP_COMMIT() asm volatile("cp.async.commit_group;")
#define CP_WAIT0()  asm volatile("cp.async.wait_group 0;")
#define CP_WAIT1()  asm volatile("cp.async.wait_group 1;")
#define CP_WAIT2()  asm volatile("cp.async.wait_group 2;")

// fp16 m16n8k16 fragment lane->address components (offsets in halves):
#define A16_ROW(lane) ((lane) & 15)
#define A16_KOF(lane) (((lane) >> 4) * 8)
#define B16_ROW(lane) (((lane) & 7) + ((lane) >> 4) * 8)
#define B16_KOF(lane) ((((lane) >> 3) & 1) * 8)

// ---------------------------------------------------------------------------
// fused fp32 -> fp16 conversion of all three inputs (8 elts/thread)
// ---------------------------------------------------------------------------
#define N_X  (BATCH * TSZ * DIM)   // 4194304
#define N_WQ (C3 * DIM)            // 3145728
#define N_WP (DIM * DIM)           // 1048576

__global__ __launch_bounds__(256)
void cvt3_f32_f16(const float* __restrict__ x, const float* __restrict__ wq,
                  const float* __restrict__ wp, __half* __restrict__ xh,
                  __half* __restrict__ wqh, __half* __restrict__ wph) {
    long i = ((long)blockIdx.x * 256 + threadIdx.x) * 8;
    const float* src;
    __half* dst;
    if (i < N_X) {
        src = x + i; dst = xh + i;
    } else if (i < (long)N_X + N_WQ) {
        src = wq + (i - N_X); dst = wqh + (i - N_X);
    } else {
        src = wp + (i - N_X - N_WQ); dst = wph + (i - N_X - N_WQ);
    }
    float4 a = *(const float4*)(src);
    float4 b = *(const float4*)(src + 4);
    *(uint4*)(dst) = f8_to_h8(a, b);
}

// ---------------------------------------------------------------------------
// FP16 GEMM (NT): C[m,n] = sum_k A[m,k]*B[n,k] (+bias[n])
// Block 128x128, BK=32, 256 thr = 8 warps (4x2), warp tile 32x64.
// 2-stage cp.async double buffer (R9-proven loop), stride 40 halves.
// __launch_bounds__(256,2): 2 CTAs/SM (regs<=124, smem 40KB).
// ---------------------------------------------------------------------------
#define BK 32
#define ASTR 40
#define SA_H (128 * ASTR)
#define SB_H (128 * ASTR)
#define STAGE_H (SA_H + SB_H)
#define GEMM_SMEM (2 * STAGE_H * 2)

template <bool BIAS, bool OUT_HALF>
__global__ __launch_bounds__(256, 2)
void f16_gemm_nt(const __half* __restrict__ A, const __half* __restrict__ B,
                 const float* __restrict__ bias, void* __restrict__ Cv,
                 int M, int N, int K) {
    extern __shared__ __half gsm[];

    const int tid  = threadIdx.x;
    const int lane = tid & 31;
    const int warp = tid >> 5;         // 0..7
    const int g = lane >> 2;
    const int t = lane & 3;
    const int wm = (warp >> 1) * 32;   // 0,32,64,96
    const int wn = (warp & 1) * 64;    // 0,64
    const int bm = blockIdx.y * 128;
    const int bn = blockIdx.x * 128;

    // staging: thread -> (row = tid>>1, 16-half chunk = (tid&1)*16)
    const int srow = tid >> 1;         // 0..127
    const int sch  = (tid & 1) * 16;   // 0,16

    const __half* Ap = A + (size_t)(bm + srow) * K + sch;
    const __half* Bp = B + (size_t)(bn + srow) * K + sch;

    const uint32_t smem0 = (uint32_t)__cvta_generic_to_shared(gsm);
    const uint32_t dR = 2u * (srow * ASTR + sch);

    const int ar = A16_ROW(lane), ak = A16_KOF(lane);
    const int br = B16_ROW(lane), bk = B16_KOF(lane);

    float acc[2][8][4];
#pragma unroll
    for (int i = 0; i < 2; i++)
#pragma unroll
        for (int j = 0; j < 8; j++)
#pragma unroll
            for (int q = 0; q < 4; q++) acc[i][j][q] = 0.f;

#define G_STAGE(slot, kt)                                                      \
    do {                                                                       \
        const uint32_t so = smem0 + 2u * (uint32_t)(slot) * STAGE_H;           \
        CP_ASYNC16(so + dR, Ap + (kt) * BK);                                   \
        CP_ASYNC16(so + dR + 16, Ap + (kt) * BK + 8);                          \
        CP_ASYNC16(so + 2u * SA_H + dR, Bp + (kt) * BK);                       \
        CP_ASYNC16(so + 2u * SA_H + dR + 16, Bp + (kt) * BK + 8);              \
        CP_COMMIT();                                                           \
    } while (0)

    const int NT = K / BK;
    G_STAGE(0, 0);

    for (int kt = 0; kt < NT; kt++) {
        const int buf = kt & 1;
        if (kt + 1 < NT) {
            G_STAGE(buf ^ 1, kt + 1);
            CP_WAIT1();
        } else {
            CP_WAIT0();
        }
        __syncthreads();

        const uint32_t aA = smem0 + 2u * (uint32_t)buf * STAGE_H;
        const uint32_t aB = aA + 2u * SA_H;
#pragma unroll
        for (int kk = 0; kk < 2; kk++) {
            uint32_t af[2][4];
#pragma unroll
            for (int mt = 0; mt < 2; mt++)
                ldsm_x4(af[mt][0], af[mt][1], af[mt][2], af[mt][3],
                        aA + 2u * ((wm + mt * 16 + ar) * ASTR + kk * 16 + ak));
#pragma unroll
            for (int p = 0; p < 4; p++) {
                uint32_t b0, b1, b2, b3;
                ldsm_x4(b0, b1, b2, b3,
                        aB + 2u * ((wn + p * 16 + br) * ASTR + kk * 16 + bk));
#pragma unroll
                for (int mt = 0; mt < 2; mt++) {
                    mma_f16(acc[mt][2 * p],     af[mt], b0, b1);
                    mma_f16(acc[mt][2 * p + 1], af[mt], b2, b3);
                }
            }
        }
        __syncthreads();  // readers done before buf overwritten next iter
    }

    // Epilogue
#pragma unroll
    for (int mt = 0; mt < 2; mt++) {
#pragma unroll
        for (int nt = 0; nt < 8; nt++) {
            const float* a4 = acc[mt][nt];
            const int row = bm + wm + mt * 16 + g;
            const int col = bn + wn + nt * 8 + 2 * t;
            if (OUT_HALF) {
                __half* C = (__half*)Cv;
                __half2 v0 = __floats2half2_rn(a4[0], a4[1]);
                __half2 v1 = __floats2half2_rn(a4[2], a4[3]);
                *(uint32_t*)&C[(size_t)row * N + col] = *(uint32_t*)&v0;
                *(uint32_t*)&C[(size_t)(row + 8) * N + col] = *(uint32_t*)&v1;
            } else {
                float* C = (float*)Cv;
                float bx = 0.f, by = 0.f;
                if (BIAS) { bx = bias[col]; by = bias[col + 1]; }
                float2 v0 = {a4[0] + bx, a4[1] + by};
                float2 v1 = {a4[2] + bx, a4[3] + by};
                *(float2*)(C + (size_t)row * N + col) = v0;
                *(float2*)(C + (size_t)(row + 8) * N + col) = v1;
            }
        }
    }
}

// ---------------------------------------------------------------------------
// FP16 flash attention (R9-proven), 2-stage cp.async KV double buffer.
// 256 threads = 8 warps, 128 q-rows, 16 kv-tiles of 64. 2 CTAs/SM.
// smem: kvbuf0{K,V}, kvbuf1{K,V} each [64][72], then sQP [128][72].
// ---------------------------------------------------------------------------
#define FSTR 72
#define KV_H (64 * FSTR)
#define FLASH_HALVES (4 * KV_H + 128 * FSTR)
#define FLASH_SMEM   (FLASH_HALVES * 2)

__global__ __launch_bounds__(256, 2)
void flash_f16(const __half* __restrict__ qkv, __half* __restrict__ att) {
    extern __shared__ __half fsm[];

    const int tid  = threadIdx.x;
    const int lane = tid & 31;
    const int warp = tid >> 5;
    const int g = lane >> 2;
    const int t = lane & 3;
    const int bh = blockIdx.y;
    const int b = bh >> 4;
    const int h = bh & 15;
    const int q0 = blockIdx.x * 128;
    const size_t base = (size_t)b * TSZ * C3;
    const int hoff = h * HDIM;
    const float qscale = 0.125f * 1.44269504088896340736f;  // scale * log2(e)

    const uint32_t smem0 = (uint32_t)__cvta_generic_to_shared(fsm);
    const uint32_t sKb[2] = {smem0, smem0 + 2u * 2 * KV_H};
    const uint32_t sVb[2] = {smem0 + 2u * KV_H, smem0 + 2u * 3 * KV_H};
    const uint32_t sQPb = smem0 + 2u * 4 * KV_H;
    const uint32_t sPwb = sQPb + 2u * (warp * 16 * FSTR);
    __half* sQP = fsm + 4 * KV_H;

    const int ar = A16_ROW(lane), ak = A16_KOF(lane);
    const int br = B16_ROW(lane), bk = B16_KOF(lane);
    const int vj = (lane & 7) + ((lane >> 3) & 1) * 8;
    const int vd = (lane >> 4) * 8;

    // Q staging (group 1): 128 rows x 8 chunks = 1024 cp, 4 per thread
#pragma unroll
    for (int it = 0; it < 4; it++) {
        const int i = tid + it * 256;
        const int r = i >> 3, c8 = (i & 7) * 8;
        CP_ASYNC16(sQPb + 2u * (r * FSTR + c8),
                   qkv + base + (size_t)(q0 + r) * C3 + hoff + c8);
    }
    CP_COMMIT();

#define KV_STAGE(bufi, kt)                                                     \
    do {                                                                       \
        const uint32_t soK = sKb[bufi];                                        \
        const uint32_t soV = sVb[bufi];                                        \
        const __half* srcb = qkv + base + (size_t)((kt) * 64) * C3 + hoff;     \
        _Pragma("unroll")                                                      \
        for (int it = 0; it < 2; it++) {                                       \
            const int i = tid + it * 256;                                      \
            const int r = i >> 3, c8 = (i & 7) * 8;                            \
            CP_ASYNC16(soK + 2u * (r * FSTR + c8),                             \
                       srcb + (size_t)r * C3 + DIM + c8);                      \
            CP_ASYNC16(soV + 2u * (r * FSTR + c8),                             \
                       srcb + (size_t)r * C3 + 2 * DIM + c8);                  \
        }                                                                      \
        CP_COMMIT();                                                           \
    } while (0)

    KV_STAGE(0, 0);

    // Wait for Q (KV group 0 may stay pending), load Q fragments
    CP_WAIT1();
    __syncthreads();
    uint32_t aq[4][4];
#pragma unroll
    for (int kk = 0; kk < 4; kk++)
        ldsm_x4(aq[kk][0], aq[kk][1], aq[kk][2], aq[kk][3],
                sQPb + 2u * ((warp * 16 + ar) * FSTR + kk * 16 + ak));

    float accO[8][4];
#pragma unroll
    for (int i = 0; i < 8; i++)
#pragma unroll
        for (int j = 0; j < 4; j++) accO[i][j] = 0.f;
    float m0 = -INFINITY, m1 = -INFINITY, l0 = 0.f, l1 = 0.f;

    for (int kt = 0; kt < 16; kt++) {
        const int buf = kt & 1;
        if (kt + 1 < 16) {
            KV_STAGE(buf ^ 1, kt + 1);
            CP_WAIT1();
        } else {
            CP_WAIT0();
        }
        __syncthreads();

        // S = Q * K^T
        float accS[8][4];
#pragma unroll
        for (int i = 0; i < 8; i++)
#pragma unroll
            for (int j = 0; j < 4; j++) accS[i][j] = 0.f;
#pragma unroll
        for (int kk = 0; kk < 4; kk++) {
#pragma unroll
            for (int p = 0; p < 4; p++) {
                uint32_t b0, b1, b2, b3;
                ldsm_x4(b0, b1, b2, b3,
                        sKb[buf] + 2u * ((p * 16 + br) * FSTR + kk * 16 + bk));
                mma_f16(accS[2 * p],     aq[kk], b0, b1);
                mma_f16(accS[2 * p + 1], aq[kk], b2, b3);
            }
        }
#pragma unroll
        for (int nt = 0; nt < 8; nt++) {
            accS[nt][0] *= qscale; accS[nt][1] *= qscale;
            accS[nt][2] *= qscale; accS[nt][3] *= qscale;
        }

        // Online softmax (rows g, g+8), base-2 domain
        float r0 = -INFINITY, r1 = -INFINITY;
#pragma unroll
        for (int nt = 0; nt < 8; nt++) {
            r0 = fmaxf(r0, fmaxf(accS[nt][0], accS[nt][1]));
            r1 = fmaxf(r1, fmaxf(accS[nt][2], accS[nt][3]));
        }
        r0 = fmaxf(r0, __shfl_xor_sync(0xffffffffu, r0, 1));
        r0 = fmaxf(r0, __shfl_xor_sync(0xffffffffu, r0, 2));
        r1 = fmaxf(r1, __shfl_xor_sync(0xffffffffu, r1, 1));
        r1 = fmaxf(r1, __shfl_xor_sync(0xffffffffu, r1, 2));
        const float mn0 = fmaxf(m0, r0);
        const float mn1 = fmaxf(m1, r1);
        const float al0 = exp2f(m0 - mn0);
        const float al1 = exp2f(m1 - mn1);
        float rs0 = 0.f, rs1 = 0.f;
        __half* sPw = sQP + warp * 16 * FSTR;
#pragma unroll
        for (int nt = 0; nt < 8; nt++) {
            __half2 h01 = __floats2half2_rn(exp2f(accS[nt][0] - mn0),
                                            exp2f(accS[nt][1] - mn0));
            __half2 h23 = __floats2half2_rn(exp2f(accS[nt][2] - mn1),
                                            exp2f(accS[nt][3] - mn1));
            float2 f01 = __half22float2(h01);
            float2 f23 = __half22float2(h23);
            rs0 += f01.x + f01.y;
            rs1 += f23.x + f23.y;
            *(uint32_t*)&sPw[g * FSTR + nt * 8 + 2 * t]       = *(uint32_t*)&h01;
            *(uint32_t*)&sPw[(g + 8) * FSTR + nt * 8 + 2 * t] = *(uint32_t*)&h23;
        }
        rs0 += __shfl_xor_sync(0xffffffffu, rs0, 1);
        rs0 += __shfl_xor_sync(0xffffffffu, rs0, 2);
        rs1 += __shfl_xor_sync(0xffffffffu, rs1, 1);
        rs1 += __shfl_xor_sync(0xffffffffu, rs1, 2);
        l0 = l0 * al0 + rs0;
        l1 = l1 * al1 + rs1;
        m0 = mn0; m1 = mn1;
#pragma unroll
        for (int nt = 0; nt < 8; nt++) {
            accO[nt][0] *= al0; accO[nt][1] *= al0;
            accO[nt][2] *= al1; accO[nt][3] *= al1;
        }
        __syncwarp();

        // O += P V (P: A-frag; V: B-frag via ldmatrix.trans)
#pragma unroll
        for (int kk = 0; kk < 4; kk++) {
            uint32_t ap[4];
            ldsm_x4(ap[0], ap[1], ap[2], ap[3],
                    sPwb + 2u * (ar * FSTR + kk * 16 + ak));
#pragma unroll
            for (int p = 0; p < 4; p++) {
                uint32_t v0, v1, v2, v3;
                ldsm_x4_trans(v0, v1, v2, v3,
                              sVb[buf] + 2u * ((kk * 16 + vj) * FSTR + p * 16 + vd));
                mma_f16(accO[2 * p],     ap, v0, v1);
                mma_f16(accO[2 * p + 1], ap, v2, v3);
            }
        }
        __syncthreads();  // readers done before buf overwritten next iter
    }

    // Epilogue: normalize, write fp16 att [B,T,C]
    const float inv0 = 1.f / l0;
    const float inv1 = 1.f / l1;
    const int r0w = q0 + warp * 16 + g;
    __half* o0 = att + (size_t)b * TSZ * DIM + (size_t)r0w * DIM + hoff;
    __half* o1 = o0 + (size_t)8 * DIM;
#pragma unroll
    for (int nt = 0; nt < 8; nt++) {
        __half2 v0 = __floats2half2_rn(accO[nt][0] * inv0, accO[nt][1] * inv0);
        __half2 v1 = __floats2half2_rn(accO[nt][2] * inv1, accO[nt][3] * inv1);
        *(uint32_t*)&o0[nt * 8 + 2 * t] = *(uint32_t*)&v0;
        *(uint32_t*)&o1[nt * 8 + 2 * t] = *(uint32_t*)&v1;
    }
}

// ---------------------------------------------------------------------------
extern "C" void kernel_launch(void* const* d_in, const int* in_sizes, int n_in,
                              void* d_out, int out_size) {
    const float* x     = (const float*)d_in[0];  // [4,1024,1024]
    const float* Wqkv  = (const float*)d_in[1];  // [3072,1024]
    const float* Wproj = (const float*)d_in[2];  // [1024,1024]
    const float* bproj = (const float*)d_in[3];  // [1024]
    float* out = (float*)d_out;                  // [4,1024,1024]

    __half *xh, *wqkvh, *wprojh, *qkvh, *atth;
    cudaGetSymbolAddress((void**)&xh, g_xh);
    cudaGetSymbolAddress((void**)&wqkvh, g_wqkvh);
    cudaGetSymbolAddress((void**)&wprojh, g_wprojh);
    cudaGetSymbolAddress((void**)&qkvh, g_qkvh);
    cudaGetSymbolAddress((void**)&atth, g_atth);

    cudaFuncSetAttribute(f16_gemm_nt<false, true>,
                         cudaFuncAttributeMaxDynamicSharedMemorySize, GEMM_SMEM);
    cudaFuncSetAttribute(f16_gemm_nt<true, false>,
                         cudaFuncAttributeMaxDynamicSharedMemorySize, GEMM_SMEM);
    cudaFuncSetAttribute(flash_f16,
                         cudaFuncAttributeMaxDynamicSharedMemorySize, FLASH_SMEM);

    // 0) fused fp32 -> fp16 conversion (x, Wqkv, Wproj)
    cvt3_f32_f16<<<(N_X + N_WQ + N_WP) / 2048, 256>>>(x, Wqkv, Wproj,
                                                      xh, wqkvh, wprojh);

    // 1) QKV projection -> fp16: [4096,1024] x [3072,1024]^T -> [4096,3072]
    f16_gemm_nt<false, true><<<dim3(C3 / 128, (BATCH * TSZ) / 128), 256,
                               GEMM_SMEM>>>(xh, wqkvh, nullptr, qkvh,
                                            BATCH * TSZ, C3, DIM);

    // 2) Attention (fp16 in/out)
    flash_f16<<<dim3(TSZ / 128, BATCH * NHEAD), 256, FLASH_SMEM>>>(qkvh, atth);

    // 3) Output projection + bias -> fp32 out
    f16_gemm_nt<true, false><<<dim3(DIM / 128, (BATCH * TSZ) / 128), 256,
                               GEMM_SMEM>>>(atth, wprojh, bproj, out,
                                            BATCH * TSZ, DIM, DIM);
}

// round 12
// speedup vs baseline: 1.4751x; 1.0469x over previous
#include <cuda_runtime.h>
#include <cuda_fp16.h>
#include <math.h>
#include <stdint.h>

// Problem constants
#define BATCH 4
#define TSZ   1024
#define DIM   1024
#define NHEAD 16
#define HDIM  64
#define C3    (3 * DIM)

// Scratch (allocation-free: __device__ globals) — fp16 pipeline
__device__ __half g_xh[BATCH * TSZ * DIM];
__device__ __half g_wqkvh[C3 * DIM];
__device__ __half g_wprojh[DIM * DIM];
__device__ __half g_qkvh[BATCH * TSZ * C3];   // [B,T,3C]
__device__ __half g_atth[BATCH * TSZ * DIM];  // [B,T,C]

// ---------------------------------------------------------------------------
// helpers
// ---------------------------------------------------------------------------
__device__ __forceinline__ void mma_f16(float c[4], const uint32_t a[4],
                                        uint32_t b0, uint32_t b1) {
    asm volatile(
        "mma.sync.aligned.m16n8k16.row.col.f32.f16.f16.f32 "
        "{%0,%1,%2,%3}, {%4,%5,%6,%7}, {%8,%9}, {%0,%1,%2,%3};"
        : "+f"(c[0]), "+f"(c[1]), "+f"(c[2]), "+f"(c[3])
        : "r"(a[0]), "r"(a[1]), "r"(a[2]), "r"(a[3]), "r"(b0), "r"(b1));
}

__device__ __forceinline__ void ldsm_x4(uint32_t& r0, uint32_t& r1, uint32_t& r2,
                                        uint32_t& r3, uint32_t saddr) {
    asm volatile(
        "ldmatrix.sync.aligned.m8n8.x4.shared.b16 {%0,%1,%2,%3}, [%4];"
        : "=r"(r0), "=r"(r1), "=r"(r2), "=r"(r3)
        : "r"(saddr));
}

__device__ __forceinline__ void ldsm_x4_trans(uint32_t& r0, uint32_t& r1,
                                              uint32_t& r2, uint32_t& r3,
                                              uint32_t saddr) {
    asm volatile(
        "ldmatrix.sync.aligned.m8n8.x4.trans.shared.b16 {%0,%1,%2,%3}, [%4];"
        : "=r"(r0), "=r"(r1), "=r"(r2), "=r"(r3)
        : "r"(saddr));
}

__device__ __forceinline__ uint4 f8_to_h8(float4 a, float4 b) {
    __half2 h0 = __floats2half2_rn(a.x, a.y);
    __half2 h1 = __floats2half2_rn(a.z, a.w);
    __half2 h2 = __floats2half2_rn(b.x, b.y);
    __half2 h3 = __floats2half2_rn(b.z, b.w);
    uint4 u;
    u.x = *(uint32_t*)&h0; u.y = *(uint32_t*)&h1;
    u.z = *(uint32_t*)&h2; u.w = *(uint32_t*)&h3;
    return u;
}

#define CP_ASYNC16(dst, src) \
    asm volatile("cp.async.cg.shared.global [%0], [%1], 16;" :: "r"(dst), "l"(src))
#define CP_COMMIT() asm volatile("cp.async.commit_group;")
#define CP_WAIT0()  asm volatile("cp.async.wait_group 0;")
#define CP_WAIT1()  asm volatile("cp.async.wait_group 1;")
#define CP_WAIT2()  asm volatile("cp.async.wait_group 2;")

// fp16 m16n8k16 fragment lane->address components (offsets in halves):
#define A16_ROW(lane) ((lane) & 15)
#define A16_KOF(lane) (((lane) >> 4) * 8)
#define B16_ROW(lane) (((lane) & 7) + ((lane) >> 4) * 8)
#define B16_KOF(lane) ((((lane) >> 3) & 1) * 8)

// ---------------------------------------------------------------------------
// fused fp32 -> fp16 conversion of all three inputs (8 elts/thread)
// ---------------------------------------------------------------------------
#define N_X  (BATCH * TSZ * DIM)   // 4194304
#define N_WQ (C3 * DIM)            // 3145728
#define N_WP (DIM * DIM)           // 1048576

__global__ __launch_bounds__(256)
void cvt3_f32_f16(const float* __restrict__ x, const float* __restrict__ wq,
                  const float* __restrict__ wp, __half* __restrict__ xh,
                  __half* __restrict__ wqh, __half* __restrict__ wph) {
    long i = ((long)blockIdx.x * 256 + threadIdx.x) * 8;
    const float* src;
    __half* dst;
    if (i < N_X) {
        src = x + i; dst = xh + i;
    } else if (i < (long)N_X + N_WQ) {
        src = wq + (i - N_X); dst = wqh + (i - N_X);
    } else {
        src = wp + (i - N_X - N_WQ); dst = wph + (i - N_X - N_WQ);
    }
    float4 a = *(const float4*)(src);
    float4 b = *(const float4*)(src + 4);
    *(uint4*)(dst) = f8_to_h8(a, b);
}

// ---------------------------------------------------------------------------
// FP16 GEMM "wide" (R9-proven): block 128x256, BK=32, 512 thr = 16 warps
// (4x4), warp tile 32x64, 2-stage cp.async, stride 40 halves. For QKV.
// ---------------------------------------------------------------------------
#define BK 32
#define ASTR 40
#define WSA_H (128 * ASTR)
#define WSB_H (256 * ASTR)
#define WSTAGE_H (WSA_H + WSB_H)
#define GEMMW_SMEM (2 * WSTAGE_H * 2)

__global__ __launch_bounds__(512, 1)
void f16_gemm_wide(const __half* __restrict__ A, const __half* __restrict__ B,
                   __half* __restrict__ C, int M, int N, int K) {
    extern __shared__ __half gsm[];

    const int tid  = threadIdx.x;
    const int lane = tid & 31;
    const int warp = tid >> 5;         // 0..15
    const int g = lane >> 2;
    const int t = lane & 3;
    const int wm = (warp >> 2) * 32;
    const int wn = (warp & 3) * 64;
    const int bm = blockIdx.y * 128;
    const int bn = blockIdx.x * 256;

    const int srow = tid >> 2;         // 0..127
    const int sch  = (tid & 3) * 8;    // 0,8,16,24

    const __half* Ap  = A + (size_t)(bm + srow) * K + sch;
    const __half* Bp0 = B + (size_t)(bn + srow) * K + sch;
    const __half* Bp1 = B + (size_t)(bn + 128 + srow) * K + sch;

    const uint32_t smem0 = (uint32_t)__cvta_generic_to_shared(gsm);
    const uint32_t dA  = 2u * (srow * ASTR + sch);
    const uint32_t dB1 = 2u * ((128 + srow) * ASTR + sch);

    const int ar = A16_ROW(lane), ak = A16_KOF(lane);
    const int br = B16_ROW(lane), bk = B16_KOF(lane);

    float acc[2][8][4];
#pragma unroll
    for (int i = 0; i < 2; i++)
#pragma unroll
        for (int j = 0; j < 8; j++)
#pragma unroll
            for (int q = 0; q < 4; q++) acc[i][j][q] = 0.f;

#define GW_STAGE(slot, kt)                                                     \
    do {                                                                       \
        const uint32_t so = smem0 + 2u * (uint32_t)(slot) * WSTAGE_H;          \
        CP_ASYNC16(so + dA, Ap + (kt) * BK);                                   \
        CP_ASYNC16(so + 2u * WSA_H + dA, Bp0 + (kt) * BK);                     \
        CP_ASYNC16(so + 2u * WSA_H + dB1, Bp1 + (kt) * BK);                    \
        CP_COMMIT();                                                           \
    } while (0)

    const int NT = K / BK;
    GW_STAGE(0, 0);

    for (int kt = 0; kt < NT; kt++) {
        const int buf = kt & 1;
        if (kt + 1 < NT) {
            GW_STAGE(buf ^ 1, kt + 1);
            CP_WAIT1();
        } else {
            CP_WAIT0();
        }
        __syncthreads();

        const uint32_t aA = smem0 + 2u * (uint32_t)buf * WSTAGE_H;
        const uint32_t aB = aA + 2u * WSA_H;
#pragma unroll
        for (int kk = 0; kk < 2; kk++) {
            uint32_t af[2][4];
#pragma unroll
            for (int mt = 0; mt < 2; mt++)
                ldsm_x4(af[mt][0], af[mt][1], af[mt][2], af[mt][3],
                        aA + 2u * ((wm + mt * 16 + ar) * ASTR + kk * 16 + ak));
#pragma unroll
            for (int p = 0; p < 4; p++) {
                uint32_t b0, b1, b2, b3;
                ldsm_x4(b0, b1, b2, b3,
                        aB + 2u * ((wn + p * 16 + br) * ASTR + kk * 16 + bk));
#pragma unroll
                for (int mt = 0; mt < 2; mt++) {
                    mma_f16(acc[mt][2 * p],     af[mt], b0, b1);
                    mma_f16(acc[mt][2 * p + 1], af[mt], b2, b3);
                }
            }
        }
        __syncthreads();
    }

    // fp16 epilogue
#pragma unroll
    for (int mt = 0; mt < 2; mt++) {
#pragma unroll
        for (int nt = 0; nt < 8; nt++) {
            const float* a4 = acc[mt][nt];
            const int row = bm + wm + mt * 16 + g;
            const int col = bn + wn + nt * 8 + 2 * t;
            __half2 v0 = __floats2half2_rn(a4[0], a4[1]);
            __half2 v1 = __floats2half2_rn(a4[2], a4[3]);
            *(uint32_t*)&C[(size_t)row * N + col] = *(uint32_t*)&v0;
            *(uint32_t*)&C[(size_t)(row + 8) * N + col] = *(uint32_t*)&v1;
        }
    }
}

// ---------------------------------------------------------------------------
// FP16 GEMM "square" (R11-proven): block 128x128, 256 thr = 8 warps (4x2),
// warp tile 32x64, 2-stage cp.async, 2 CTAs/SM. fp32 output + bias. For proj.
// ---------------------------------------------------------------------------
#define SSA_H (128 * ASTR)
#define SSTAGE_H (2 * SSA_H)
#define GEMMS_SMEM (2 * SSTAGE_H * 2)

__global__ __launch_bounds__(256, 2)
void f16_gemm_sq(const __half* __restrict__ A, const __half* __restrict__ B,
                 const float* __restrict__ bias, float* __restrict__ C,
                 int M, int N, int K) {
    extern __shared__ __half gsm[];

    const int tid  = threadIdx.x;
    const int lane = tid & 31;
    const int warp = tid >> 5;         // 0..7
    const int g = lane >> 2;
    const int t = lane & 3;
    const int wm = (warp >> 1) * 32;
    const int wn = (warp & 1) * 64;
    const int bm = blockIdx.y * 128;
    const int bn = blockIdx.x * 128;

    const int srow = tid >> 1;         // 0..127
    const int sch  = (tid & 1) * 16;   // 0,16

    const __half* Ap = A + (size_t)(bm + srow) * K + sch;
    const __half* Bp = B + (size_t)(bn + srow) * K + sch;

    const uint32_t smem0 = (uint32_t)__cvta_generic_to_shared(gsm);
    const uint32_t dR = 2u * (srow * ASTR + sch);

    const int ar = A16_ROW(lane), ak = A16_KOF(lane);
    const int br = B16_ROW(lane), bk = B16_KOF(lane);

    float acc[2][8][4];
#pragma unroll
    for (int i = 0; i < 2; i++)
#pragma unroll
        for (int j = 0; j < 8; j++)
#pragma unroll
            for (int q = 0; q < 4; q++) acc[i][j][q] = 0.f;

#define GS_STAGE(slot, kt)                                                     \
    do {                                                                       \
        const uint32_t so = smem0 + 2u * (uint32_t)(slot) * SSTAGE_H;          \
        CP_ASYNC16(so + dR, Ap + (kt) * BK);                                   \
        CP_ASYNC16(so + dR + 16, Ap + (kt) * BK + 8);                          \
        CP_ASYNC16(so + 2u * SSA_H + dR, Bp + (kt) * BK);                      \
        CP_ASYNC16(so + 2u * SSA_H + dR + 16, Bp + (kt) * BK + 8);             \
        CP_COMMIT();                                                           \
    } while (0)

    const int NT = K / BK;
    GS_STAGE(0, 0);

    for (int kt = 0; kt < NT; kt++) {
        const int buf = kt & 1;
        if (kt + 1 < NT) {
            GS_STAGE(buf ^ 1, kt + 1);
            CP_WAIT1();
        } else {
            CP_WAIT0();
        }
        __syncthreads();

        const uint32_t aA = smem0 + 2u * (uint32_t)buf * SSTAGE_H;
        const uint32_t aB = aA + 2u * SSA_H;
#pragma unroll
        for (int kk = 0; kk < 2; kk++) {
            uint32_t af[2][4];
#pragma unroll
            for (int mt = 0; mt < 2; mt++)
                ldsm_x4(af[mt][0], af[mt][1], af[mt][2], af[mt][3],
                        aA + 2u * ((wm + mt * 16 + ar) * ASTR + kk * 16 + ak));
#pragma unroll
            for (int p = 0; p < 4; p++) {
                uint32_t b0, b1, b2, b3;
                ldsm_x4(b0, b1, b2, b3,
                        aB + 2u * ((wn + p * 16 + br) * ASTR + kk * 16 + bk));
#pragma unroll
                for (int mt = 0; mt < 2; mt++) {
                    mma_f16(acc[mt][2 * p],     af[mt], b0, b1);
                    mma_f16(acc[mt][2 * p + 1], af[mt], b2, b3);
                }
            }
        }
        __syncthreads();
    }

    // fp32 epilogue + bias
#pragma unroll
    for (int mt = 0; mt < 2; mt++) {
#pragma unroll
        for (int nt = 0; nt < 8; nt++) {
            const float* a4 = acc[mt][nt];
            const int row = bm + wm + mt * 16 + g;
            const int col = bn + wn + nt * 8 + 2 * t;
            float bx = bias[col], by = bias[col + 1];
            float2 v0 = {a4[0] + bx, a4[1] + by};
            float2 v1 = {a4[2] + bx, a4[3] + by};
            *(float2*)(C + (size_t)row * N + col) = v0;
            *(float2*)(C + (size_t)(row + 8) * N + col) = v1;
        }
    }
}

// ---------------------------------------------------------------------------
// FP16 flash attention — register-resident P (S C-frag == P A-frag layout).
// 256 threads = 8 warps, 128 q-rows, 16 kv-tiles of 64, 2-stage cp.async KV.
// smem: kvbuf0{K,V}, kvbuf1{K,V} each [64][72], then sQ [128][72].
// ---------------------------------------------------------------------------
#define FSTR 72
#define KV_H (64 * FSTR)
#define FLASH_HALVES (4 * KV_H + 128 * FSTR)
#define FLASH_SMEM   (FLASH_HALVES * 2)

__global__ __launch_bounds__(256, 2)
void flash_f16(const __half* __restrict__ qkv, __half* __restrict__ att) {
    extern __shared__ __half fsm[];

    const int tid  = threadIdx.x;
    const int lane = tid & 31;
    const int warp = tid >> 5;
    const int g = lane >> 2;
    const int t = lane & 3;
    const int bh = blockIdx.y;
    const int b = bh >> 4;
    const int h = bh & 15;
    const int q0 = blockIdx.x * 128;
    const size_t base = (size_t)b * TSZ * C3;
    const int hoff = h * HDIM;
    const float qscale = 0.125f * 1.44269504088896340736f;  // scale * log2(e)

    const uint32_t smem0 = (uint32_t)__cvta_generic_to_shared(fsm);
    const uint32_t sKb[2] = {smem0, smem0 + 2u * 2 * KV_H};
    const uint32_t sVb[2] = {smem0 + 2u * KV_H, smem0 + 2u * 3 * KV_H};
    const uint32_t sQb = smem0 + 2u * 4 * KV_H;

    const int ar = A16_ROW(lane), ak = A16_KOF(lane);
    const int br = B16_ROW(lane), bk = B16_KOF(lane);
    const int vj = (lane & 7) + ((lane >> 3) & 1) * 8;
    const int vd = (lane >> 4) * 8;

    // Q staging (group 1)
#pragma unroll
    for (int it = 0; it < 4; it++) {
        const int i = tid + it * 256;
        const int r = i >> 3, c8 = (i & 7) * 8;
        CP_ASYNC16(sQb + 2u * (r * FSTR + c8),
                   qkv + base + (size_t)(q0 + r) * C3 + hoff + c8);
    }
    CP_COMMIT();

#define KV_STAGE(bufi, kt)                                                     \
    do {                                                                       \
        const uint32_t soK = sKb[bufi];                                        \
        const uint32_t soV = sVb[bufi];                                        \
        const __half* srcb = qkv + base + (size_t)((kt) * 64) * C3 + hoff;     \
        _Pragma("unroll")                                                      \
        for (int it = 0; it < 2; it++) {                                       \
            const int i = tid + it * 256;                                      \
            const int r = i >> 3, c8 = (i & 7) * 8;                            \
            CP_ASYNC16(soK + 2u * (r * FSTR + c8),                             \
                       srcb + (size_t)r * C3 + DIM + c8);                      \
            CP_ASYNC16(soV + 2u * (r * FSTR + c8),                             \
                       srcb + (size_t)r * C3 + 2 * DIM + c8);                  \
        }                                                                      \
        CP_COMMIT();                                                           \
    } while (0)

    KV_STAGE(0, 0);

    // Wait for Q (KV group 0 may stay pending), load Q fragments
    CP_WAIT1();
    __syncthreads();
    uint32_t aq[4][4];
#pragma unroll
    for (int kk = 0; kk < 4; kk++)
        ldsm_x4(aq[kk][0], aq[kk][1], aq[kk][2], aq[kk][3],
                sQb + 2u * ((warp * 16 + ar) * FSTR + kk * 16 + ak));

    float accO[8][4];
#pragma unroll
    for (int i = 0; i < 8; i++)
#pragma unroll
        for (int j = 0; j < 4; j++) accO[i][j] = 0.f;
    float m0 = -INFINITY, m1 = -INFINITY, l0 = 0.f, l1 = 0.f;

    for (int kt = 0; kt < 16; kt++) {
        const int buf = kt & 1;
        if (kt + 1 < 16) {
            KV_STAGE(buf ^ 1, kt + 1);
            CP_WAIT1();
        } else {
            CP_WAIT0();
        }
        __syncthreads();

        // S = Q * K^T
        float accS[8][4];
#pragma unroll
        for (int i = 0; i < 8; i++)
#pragma unroll
            for (int j = 0; j < 4; j++) accS[i][j] = 0.f;
#pragma unroll
        for (int kk = 0; kk < 4; kk++) {
#pragma unroll
            for (int p = 0; p < 4; p++) {
                uint32_t b0, b1, b2, b3;
                ldsm_x4(b0, b1, b2, b3,
                        sKb[buf] + 2u * ((p * 16 + br) * FSTR + kk * 16 + bk));
                mma_f16(accS[2 * p],     aq[kk], b0, b1);
                mma_f16(accS[2 * p + 1], aq[kk], b2, b3);
            }
        }
#pragma unroll
        for (int nt = 0; nt < 8; nt++) {
            accS[nt][0] *= qscale; accS[nt][1] *= qscale;
            accS[nt][2] *= qscale; accS[nt][3] *= qscale;
        }

        // Online softmax (rows g, g+8), base-2 domain
        float r0 = -INFINITY, r1 = -INFINITY;
#pragma unroll
        for (int nt = 0; nt < 8; nt++) {
            r0 = fmaxf(r0, fmaxf(accS[nt][0], accS[nt][1]));
            r1 = fmaxf(r1, fmaxf(accS[nt][2], accS[nt][3]));
        }
        r0 = fmaxf(r0, __shfl_xor_sync(0xffffffffu, r0, 1));
        r0 = fmaxf(r0, __shfl_xor_sync(0xffffffffu, r0, 2));
        r1 = fmaxf(r1, __shfl_xor_sync(0xffffffffu, r1, 1));
        r1 = fmaxf(r1, __shfl_xor_sync(0xffffffffu, r1, 2));
        const float mn0 = fmaxf(m0, r0);
        const float mn1 = fmaxf(m1, r1);
        const float al0 = exp2f(m0 - mn0);
        const float al1 = exp2f(m1 - mn1);
        float rs0 = 0.f, rs1 = 0.f;

        // P directly as A-fragments: phA[nt] = rows g (cols nt*8+2t,2t+1),
        // phB[nt] = rows g+8. (C-frag of S == A-frag of P layout identity.)
        uint32_t phA[8], phB[8];
#pragma unroll
        for (int nt = 0; nt < 8; nt++) {
            __half2 h01 = __floats2half2_rn(exp2f(accS[nt][0] - mn0),
                                            exp2f(accS[nt][1] - mn0));
            __half2 h23 = __floats2half2_rn(exp2f(accS[nt][2] - mn1),
                                            exp2f(accS[nt][3] - mn1));
            float2 f01 = __half22float2(h01);
            float2 f23 = __half22float2(h23);
            rs0 += f01.x + f01.y;
            rs1 += f23.x + f23.y;
            phA[nt] = *(uint32_t*)&h01;
            phB[nt] = *(uint32_t*)&h23;
        }
        rs0 += __shfl_xor_sync(0xffffffffu, rs0, 1);
        rs0 += __shfl_xor_sync(0xffffffffu, rs0, 2);
        rs1 += __shfl_xor_sync(0xffffffffu, rs1, 1);
        rs1 += __shfl_xor_sync(0xffffffffu, rs1, 2);
        l0 = l0 * al0 + rs0;
        l1 = l1 * al1 + rs1;
        m0 = mn0; m1 = mn1;
#pragma unroll
        for (int nt = 0; nt < 8; nt++) {
            accO[nt][0] *= al0; accO[nt][1] *= al0;
            accO[nt][2] *= al1; accO[nt][3] *= al1;
        }

        // O += P V (P from registers; V: B-frag via ldmatrix.trans)
#pragma unroll
        for (int kk = 0; kk < 4; kk++) {
            uint32_t ap[4];
            ap[0] = phA[2 * kk];
            ap[1] = phB[2 * kk];
            ap[2] = phA[2 * kk + 1];
            ap[3] = phB[2 * kk + 1];
#pragma unroll
            for (int p = 0; p < 4; p++) {
                uint32_t v0, v1, v2, v3;
                ldsm_x4_trans(v0, v1, v2, v3,
                              sVb[buf] + 2u * ((kk * 16 + vj) * FSTR + p * 16 + vd));
                mma_f16(accO[2 * p],     ap, v0, v1);
                mma_f16(accO[2 * p + 1], ap, v2, v3);
            }
        }
        __syncthreads();  // readers done before buf overwritten next iter
    }

    // Epilogue: normalize, write fp16 att [B,T,C]
    const float inv0 = 1.f / l0;
    const float inv1 = 1.f / l1;
    const int r0w = q0 + warp * 16 + g;
    __half* o0 = att + (size_t)b * TSZ * DIM + (size_t)r0w * DIM + hoff;
    __half* o1 = o0 + (size_t)8 * DIM;
#pragma unroll
    for (int nt = 0; nt < 8; nt++) {
        __half2 v0 = __floats2half2_rn(accO[nt][0] * inv0, accO[nt][1] * inv0);
        __half2 v1 = __floats2half2_rn(accO[nt][2] * inv1, accO[nt][3] * inv1);
        *(uint32_t*)&o0[nt * 8 + 2 * t] = *(uint32_t*)&v0;
        *(uint32_t*)&o1[nt * 8 + 2 * t] = *(uint32_t*)&v1;
    }
}

// ---------------------------------------------------------------------------
extern "C" void kernel_launch(void* const* d_in, const int* in_sizes, int n_in,
                              void* d_out, int out_size) {
    const float* x     = (const float*)d_in[0];  // [4,1024,1024]
    const float* Wqkv  = (const float*)d_in[1];  // [3072,1024]
    const float* Wproj = (const float*)d_in[2];  // [1024,1024]
    const float* bproj = (const float*)d_in[3];  // [1024]
    float* out = (float*)d_out;                  // [4,1024,1024]

    __half *xh, *wqkvh, *wprojh, *qkvh, *atth;
    cudaGetSymbolAddress((void**)&xh, g_xh);
    cudaGetSymbolAddress((void**)&wqkvh, g_wqkvh);
    cudaGetSymbolAddress((void**)&wprojh, g_wprojh);
    cudaGetSymbolAddress((void**)&qkvh, g_qkvh);
    cudaGetSymbolAddress((void**)&atth, g_atth);

    cudaFuncSetAttribute(f16_gemm_wide,
                         cudaFuncAttributeMaxDynamicSharedMemorySize, GEMMW_SMEM);
    cudaFuncSetAttribute(f16_gemm_sq,
                         cudaFuncAttributeMaxDynamicSharedMemorySize, GEMMS_SMEM);
    cudaFuncSetAttribute(flash_f16,
                         cudaFuncAttributeMaxDynamicSharedMemorySize, FLASH_SMEM);

    // 0) fused fp32 -> fp16 conversion (x, Wqkv, Wproj)
    cvt3_f32_f16<<<(N_X + N_WQ + N_WP) / 2048, 256>>>(x, Wqkv, Wproj,
                                                      xh, wqkvh, wprojh);

    // 1) QKV projection -> fp16: [4096,1024] x [3072,1024]^T -> [4096,3072]
    f16_gemm_wide<<<dim3(C3 / 256, (BATCH * TSZ) / 128), 512, GEMMW_SMEM>>>(
        xh, wqkvh, qkvh, BATCH * TSZ, C3, DIM);

    // 2) Attention (fp16 in/out, register-resident P)
    flash_f16<<<dim3(TSZ / 128, BATCH * NHEAD), 256, FLASH_SMEM>>>(qkvh, atth);

    // 3) Output projection + bias -> fp32 out
    f16_gemm_sq<<<dim3(DIM / 128, (BATCH * TSZ) / 128), 256, GEMMS_SMEM>>>(
        atth, wprojh, bproj, out, BATCH * TSZ, DIM, DIM);
}

// round 13
// speedup vs baseline: 1.5116x; 1.0248x over previous
#include <cuda_runtime.h>
#include <cuda_fp16.h>
#include <math.h>
#include <stdint.h>

// Problem constants
#define BATCH 4
#define TSZ   1024
#define DIM   1024
#define NHEAD 16
#define HDIM  64
#define C3    (3 * DIM)

// Scratch (allocation-free: __device__ globals) — fp16 pipeline
__device__ __half g_xh[BATCH * TSZ * DIM];
__device__ __half g_wqkvh[C3 * DIM];
__device__ __half g_wprojh[DIM * DIM];
__device__ __half g_qkvh[BATCH * TSZ * C3];   // [B,T,3C]
__device__ __half g_atth[BATCH * TSZ * DIM];  // [B,T,C]

// ---------------------------------------------------------------------------
// helpers
// ---------------------------------------------------------------------------
__device__ __forceinline__ void mma_f16(float c[4], const uint32_t a[4],
                                        uint32_t b0, uint32_t b1) {
    asm volatile(
        "mma.sync.aligned.m16n8k16.row.col.f32.f16.f16.f32 "
        "{%0,%1,%2,%3}, {%4,%5,%6,%7}, {%8,%9}, {%0,%1,%2,%3};"
        : "+f"(c[0]), "+f"(c[1]), "+f"(c[2]), "+f"(c[3])
        : "r"(a[0]), "r"(a[1]), "r"(a[2]), "r"(a[3]), "r"(b0), "r"(b1));
}

__device__ __forceinline__ void ldsm_x4(uint32_t& r0, uint32_t& r1, uint32_t& r2,
                                        uint32_t& r3, uint32_t saddr) {
    asm volatile(
        "ldmatrix.sync.aligned.m8n8.x4.shared.b16 {%0,%1,%2,%3}, [%4];"
        : "=r"(r0), "=r"(r1), "=r"(r2), "=r"(r3)
        : "r"(saddr));
}

__device__ __forceinline__ void ldsm_x4_trans(uint32_t& r0, uint32_t& r1,
                                              uint32_t& r2, uint32_t& r3,
                                              uint32_t saddr) {
    asm volatile(
        "ldmatrix.sync.aligned.m8n8.x4.trans.shared.b16 {%0,%1,%2,%3}, [%4];"
        : "=r"(r0), "=r"(r1), "=r"(r2), "=r"(r3)
        : "r"(saddr));
}

__device__ __forceinline__ uint4 f8_to_h8(float4 a, float4 b) {
    __half2 h0 = __floats2half2_rn(a.x, a.y);
    __half2 h1 = __floats2half2_rn(a.z, a.w);
    __half2 h2 = __floats2half2_rn(b.x, b.y);
    __half2 h3 = __floats2half2_rn(b.z, b.w);
    uint4 u;
    u.x = *(uint32_t*)&h0; u.y = *(uint32_t*)&h1;
    u.z = *(uint32_t*)&h2; u.w = *(uint32_t*)&h3;
    return u;
}

#define CP_ASYNC16(dst, src) \
    asm volatile("cp.async.cg.shared.global [%0], [%1], 16;" :: "r"(dst), "l"(src))
#define CP_COMMIT() asm volatile("cp.async.commit_group;")
#define CP_WAIT0()  asm volatile("cp.async.wait_group 0;")
#define CP_WAIT1()  asm volatile("cp.async.wait_group 1;")

// fp16 m16n8k16 fragment lane->address components (offsets in halves):
#define A16_ROW(lane) ((lane) & 15)
#define A16_KOF(lane) (((lane) >> 4) * 8)
#define B16_ROW(lane) (((lane) & 7) + ((lane) >> 4) * 8)
#define B16_KOF(lane) ((((lane) >> 3) & 1) * 8)

// ---------------------------------------------------------------------------
// fused fp32 -> fp16 conversion of all three inputs (8 elts/thread)
// ---------------------------------------------------------------------------
#define N_X  (BATCH * TSZ * DIM)   // 4194304
#define N_WQ (C3 * DIM)            // 3145728
#define N_WP (DIM * DIM)           // 1048576

__global__ __launch_bounds__(256)
void cvt3_f32_f16(const float* __restrict__ x, const float* __restrict__ wq,
                  const float* __restrict__ wp, __half* __restrict__ xh,
                  __half* __restrict__ wqh, __half* __restrict__ wph) {
    long i = ((long)blockIdx.x * 256 + threadIdx.x) * 8;
    const float* src;
    __half* dst;
    if (i < N_X) {
        src = x + i; dst = xh + i;
    } else if (i < (long)N_X + N_WQ) {
        src = wq + (i - N_X); dst = wqh + (i - N_X);
    } else {
        src = wp + (i - N_X - N_WQ); dst = wph + (i - N_X - N_WQ);
    }
    float4 a = *(const float4*)(src);
    float4 b = *(const float4*)(src + 4);
    *(uint4*)(dst) = f8_to_h8(a, b);
}

// ---------------------------------------------------------------------------
// FP16 GEMM "wide" — BK=64 variant: block 128x256, 512 thr = 16 warps (4x4),
// warp tile 32x64, 2-stage cp.async, stride 72 halves (conflict-free ldsm).
// ONE k-iter = 64 k (4 k16 groups); 16 iters total; 108 KB smem. For QKV.
// ---------------------------------------------------------------------------
#define WBK 64
#define WSTR 72
#define WSA_H (128 * WSTR)
#define WSB_H (256 * WSTR)
#define WSTAGE_H (WSA_H + WSB_H)
#define GEMMW_SMEM (2 * WSTAGE_H * 2)   // 110592 bytes

__global__ __launch_bounds__(512, 1)
void f16_gemm_wide(const __half* __restrict__ A, const __half* __restrict__ B,
                   __half* __restrict__ C, int M, int N, int K) {
    extern __shared__ __half gsm[];

    const int tid  = threadIdx.x;
    const int lane = tid & 31;
    const int warp = tid >> 5;         // 0..15
    const int g = lane >> 2;
    const int t = lane & 3;
    const int wm = (warp >> 2) * 32;
    const int wn = (warp & 3) * 64;
    const int bm = blockIdx.y * 128;
    const int bn = blockIdx.x * 256;

    // staging: thread -> (row = tid>>2, 16-half chunk = (tid&3)*16)
    const int srow = tid >> 2;         // 0..127
    const int sch  = (tid & 3) * 16;   // 0,16,32,48

    const __half* Ap  = A + (size_t)(bm + srow) * K + sch;
    const __half* Bp0 = B + (size_t)(bn + srow) * K + sch;
    const __half* Bp1 = B + (size_t)(bn + 128 + srow) * K + sch;

    const uint32_t smem0 = (uint32_t)__cvta_generic_to_shared(gsm);
    const uint32_t dR  = 2u * (srow * WSTR + sch);
    const uint32_t dB1 = 2u * ((128 + srow) * WSTR + sch);

    const int ar = A16_ROW(lane), ak = A16_KOF(lane);
    const int br = B16_ROW(lane), bk = B16_KOF(lane);

    float acc[2][8][4];
#pragma unroll
    for (int i = 0; i < 2; i++)
#pragma unroll
        for (int j = 0; j < 8; j++)
#pragma unroll
            for (int q = 0; q < 4; q++) acc[i][j][q] = 0.f;

#define GW_STAGE(slot, kt)                                                     \
    do {                                                                       \
        const uint32_t so = smem0 + 2u * (uint32_t)(slot) * WSTAGE_H;          \
        CP_ASYNC16(so + dR, Ap + (kt) * WBK);                                  \
        CP_ASYNC16(so + dR + 16, Ap + (kt) * WBK + 8);                         \
        CP_ASYNC16(so + 2u * WSA_H + dR, Bp0 + (kt) * WBK);                    \
        CP_ASYNC16(so + 2u * WSA_H + dR + 16, Bp0 + (kt) * WBK + 8);           \
        CP_ASYNC16(so + 2u * WSA_H + dB1, Bp1 + (kt) * WBK);                   \
        CP_ASYNC16(so + 2u * WSA_H + dB1 + 16, Bp1 + (kt) * WBK + 8);          \
        CP_COMMIT();                                                           \
    } while (0)

    const int NT = K / WBK;   // 16
    GW_STAGE(0, 0);

    for (int kt = 0; kt < NT; kt++) {
        const int buf = kt & 1;
        if (kt + 1 < NT) {
            GW_STAGE(buf ^ 1, kt + 1);
            CP_WAIT1();
        } else {
            CP_WAIT0();
        }
        __syncthreads();

        const uint32_t aA = smem0 + 2u * (uint32_t)buf * WSTAGE_H;
        const uint32_t aB = aA + 2u * WSA_H;
#pragma unroll
        for (int kk = 0; kk < 4; kk++) {   // four k16 per WBK=64
            uint32_t af[2][4];
#pragma unroll
            for (int mt = 0; mt < 2; mt++)
                ldsm_x4(af[mt][0], af[mt][1], af[mt][2], af[mt][3],
                        aA + 2u * ((wm + mt * 16 + ar) * WSTR + kk * 16 + ak));
#pragma unroll
            for (int p = 0; p < 4; p++) {
                uint32_t b0, b1, b2, b3;
                ldsm_x4(b0, b1, b2, b3,
                        aB + 2u * ((wn + p * 16 + br) * WSTR + kk * 16 + bk));
#pragma unroll
                for (int mt = 0; mt < 2; mt++) {
                    mma_f16(acc[mt][2 * p],     af[mt], b0, b1);
                    mma_f16(acc[mt][2 * p + 1], af[mt], b2, b3);
                }
            }
        }
        __syncthreads();
    }

    // fp16 epilogue
#pragma unroll
    for (int mt = 0; mt < 2; mt++) {
#pragma unroll
        for (int nt = 0; nt < 8; nt++) {
            const float* a4 = acc[mt][nt];
            const int row = bm + wm + mt * 16 + g;
            const int col = bn + wn + nt * 8 + 2 * t;
            __half2 v0 = __floats2half2_rn(a4[0], a4[1]);
            __half2 v1 = __floats2half2_rn(a4[2], a4[3]);
            *(uint32_t*)&C[(size_t)row * N + col] = *(uint32_t*)&v0;
            *(uint32_t*)&C[(size_t)(row + 8) * N + col] = *(uint32_t*)&v1;
        }
    }
}

// ---------------------------------------------------------------------------
// FP16 GEMM "square" (R11/R12-proven): block 128x128, 256 thr = 8 warps (4x2),
// warp tile 32x64, BK=32, 2-stage cp.async, 2 CTAs/SM. fp32 out + bias. Proj.
// ---------------------------------------------------------------------------
#define BK 32
#define ASTR 40
#define SSA_H (128 * ASTR)
#define SSTAGE_H (2 * SSA_H)
#define GEMMS_SMEM (2 * SSTAGE_H * 2)

__global__ __launch_bounds__(256, 2)
void f16_gemm_sq(const __half* __restrict__ A, const __half* __restrict__ B,
                 const float* __restrict__ bias, float* __restrict__ C,
                 int M, int N, int K) {
    extern __shared__ __half gsm[];

    const int tid  = threadIdx.x;
    const int lane = tid & 31;
    const int warp = tid >> 5;         // 0..7
    const int g = lane >> 2;
    const int t = lane & 3;
    const int wm = (warp >> 1) * 32;
    const int wn = (warp & 1) * 64;
    const int bm = blockIdx.y * 128;
    const int bn = blockIdx.x * 128;

    const int srow = tid >> 1;         // 0..127
    const int sch  = (tid & 1) * 16;   // 0,16

    const __half* Ap = A + (size_t)(bm + srow) * K + sch;
    const __half* Bp = B + (size_t)(bn + srow) * K + sch;

    const uint32_t smem0 = (uint32_t)__cvta_generic_to_shared(gsm);
    const uint32_t dR = 2u * (srow * ASTR + sch);

    const int ar = A16_ROW(lane), ak = A16_KOF(lane);
    const int br = B16_ROW(lane), bk = B16_KOF(lane);

    float acc[2][8][4];
#pragma unroll
    for (int i = 0; i < 2; i++)
#pragma unroll
        for (int j = 0; j < 8; j++)
#pragma unroll
            for (int q = 0; q < 4; q++) acc[i][j][q] = 0.f;

#define GS_STAGE(slot, kt)                                                     \
    do {                                                                       \
        const uint32_t so = smem0 + 2u * (uint32_t)(slot) * SSTAGE_H;          \
        CP_ASYNC16(so + dR, Ap + (kt) * BK);                                   \
        CP_ASYNC16(so + dR + 16, Ap + (kt) * BK + 8);                          \
        CP_ASYNC16(so + 2u * SSA_H + dR, Bp + (kt) * BK);                      \
        CP_ASYNC16(so + 2u * SSA_H + dR + 16, Bp + (kt) * BK + 8);             \
        CP_COMMIT();                                                           \
    } while (0)

    const int NT = K / BK;
    GS_STAGE(0, 0);

    for (int kt = 0; kt < NT; kt++) {
        const int buf = kt & 1;
        if (kt + 1 < NT) {
            GS_STAGE(buf ^ 1, kt + 1);
            CP_WAIT1();
        } else {
            CP_WAIT0();
        }
        __syncthreads();

        const uint32_t aA = smem0 + 2u * (uint32_t)buf * SSTAGE_H;
        const uint32_t aB = aA + 2u * SSA_H;
#pragma unroll
        for (int kk = 0; kk < 2; kk++) {
            uint32_t af[2][4];
#pragma unroll
            for (int mt = 0; mt < 2; mt++)
                ldsm_x4(af[mt][0], af[mt][1], af[mt][2], af[mt][3],
                        aA + 2u * ((wm + mt * 16 + ar) * ASTR + kk * 16 + ak));
#pragma unroll
            for (int p = 0; p < 4; p++) {
                uint32_t b0, b1, b2, b3;
                ldsm_x4(b0, b1, b2, b3,
                        aB + 2u * ((wn + p * 16 + br) * ASTR + kk * 16 + bk));
#pragma unroll
                for (int mt = 0; mt < 2; mt++) {
                    mma_f16(acc[mt][2 * p],     af[mt], b0, b1);
                    mma_f16(acc[mt][2 * p + 1], af[mt], b2, b3);
                }
            }
        }
        __syncthreads();
    }

    // fp32 epilogue + bias
#pragma unroll
    for (int mt = 0; mt < 2; mt++) {
#pragma unroll
        for (int nt = 0; nt < 8; nt++) {
            const float* a4 = acc[mt][nt];
            const int row = bm + wm + mt * 16 + g;
            const int col = bn + wn + nt * 8 + 2 * t;
            float bx = bias[col], by = bias[col + 1];
            float2 v0 = {a4[0] + bx, a4[1] + by};
            float2 v1 = {a4[2] + bx, a4[3] + by};
            *(float2*)(C + (size_t)row * N + col) = v0;
            *(float2*)(C + (size_t)(row + 8) * N + col) = v1;
        }
    }
}

// ---------------------------------------------------------------------------
// FP16 flash attention (R12-proven) — register-resident P.
// 256 threads = 8 warps, 128 q-rows, 16 kv-tiles of 64, 2-stage cp.async KV.
// ---------------------------------------------------------------------------
#define FSTR 72
#define KV_H (64 * FSTR)
#define FLASH_HALVES (4 * KV_H + 128 * FSTR)
#define FLASH_SMEM   (FLASH_HALVES * 2)

__global__ __launch_bounds__(256, 2)
void flash_f16(const __half* __restrict__ qkv, __half* __restrict__ att) {
    extern __shared__ __half fsm[];

    const int tid  = threadIdx.x;
    const int lane = tid & 31;
    const int warp = tid >> 5;
    const int g = lane >> 2;
    const int t = lane & 3;
    const int bh = blockIdx.y;
    const int b = bh >> 4;
    const int h = bh & 15;
    const int q0 = blockIdx.x * 128;
    const size_t base = (size_t)b * TSZ * C3;
    const int hoff = h * HDIM;
    const float qscale = 0.125f * 1.44269504088896340736f;  // scale * log2(e)

    const uint32_t smem0 = (uint32_t)__cvta_generic_to_shared(fsm);
    const uint32_t sKb[2] = {smem0, smem0 + 2u * 2 * KV_H};
    const uint32_t sVb[2] = {smem0 + 2u * KV_H, smem0 + 2u * 3 * KV_H};
    const uint32_t sQb = smem0 + 2u * 4 * KV_H;

    const int ar = A16_ROW(lane), ak = A16_KOF(lane);
    const int br = B16_ROW(lane), bk = B16_KOF(lane);
    const int vj = (lane & 7) + ((lane >> 3) & 1) * 8;
    const int vd = (lane >> 4) * 8;

    // Q staging (group 1)
#pragma unroll
    for (int it = 0; it < 4; it++) {
        const int i = tid + it * 256;
        const int r = i >> 3, c8 = (i & 7) * 8;
        CP_ASYNC16(sQb + 2u * (r * FSTR + c8),
                   qkv + base + (size_t)(q0 + r) * C3 + hoff + c8);
    }
    CP_COMMIT();

#define KV_STAGE(bufi, kt)                                                     \
    do {                                                                       \
        const uint32_t soK = sKb[bufi];                                        \
        const uint32_t soV = sVb[bufi];                                        \
        const __half* srcb = qkv + base + (size_t)((kt) * 64) * C3 + hoff;     \
        _Pragma("unroll")                                                      \
        for (int it = 0; it < 2; it++) {                                       \
            const int i = tid + it * 256;                                      \
            const int r = i >> 3, c8 = (i & 7) * 8;                            \
            CP_ASYNC16(soK + 2u * (r * FSTR + c8),                             \
                       srcb + (size_t)r * C3 + DIM + c8);                      \
            CP_ASYNC16(soV + 2u * (r * FSTR + c8),                             \
                       srcb + (size_t)r * C3 + 2 * DIM + c8);                  \
        }                                                                      \
        CP_COMMIT();                                                           \
    } while (0)

    KV_STAGE(0, 0);

    // Wait for Q (KV group 0 may stay pending), load Q fragments
    CP_WAIT1();
    __syncthreads();
    uint32_t aq[4][4];
#pragma unroll
    for (int kk = 0; kk < 4; kk++)
        ldsm_x4(aq[kk][0], aq[kk][1], aq[kk][2], aq[kk][3],
                sQb + 2u * ((warp * 16 + ar) * FSTR + kk * 16 + ak));

    float accO[8][4];
#pragma unroll
    for (int i = 0; i < 8; i++)
#pragma unroll
        for (int j = 0; j < 4; j++) accO[i][j] = 0.f;
    float m0 = -INFINITY, m1 = -INFINITY, l0 = 0.f, l1 = 0.f;

    for (int kt = 0; kt < 16; kt++) {
        const int buf = kt & 1;
        if (kt + 1 < 16) {
            KV_STAGE(buf ^ 1, kt + 1);
            CP_WAIT1();
        } else {
            CP_WAIT0();
        }
        __syncthreads();

        // S = Q * K^T
        float accS[8][4];
#pragma unroll
        for (int i = 0; i < 8; i++)
#pragma unroll
            for (int j = 0; j < 4; j++) accS[i][j] = 0.f;
#pragma unroll
        for (int kk = 0; kk < 4; kk++) {
#pragma unroll
            for (int p = 0; p < 4; p++) {
                uint32_t b0, b1, b2, b3;
                ldsm_x4(b0, b1, b2, b3,
                        sKb[buf] + 2u * ((p * 16 + br) * FSTR + kk * 16 + bk));
                mma_f16(accS[2 * p],     aq[kk], b0, b1);
                mma_f16(accS[2 * p + 1], aq[kk], b2, b3);
            }
        }
#pragma unroll
        for (int nt = 0; nt < 8; nt++) {
            accS[nt][0] *= qscale; accS[nt][1] *= qscale;
            accS[nt][2] *= qscale; accS[nt][3] *= qscale;
        }

        // Online softmax (rows g, g+8), base-2 domain
        float r0 = -INFINITY, r1 = -INFINITY;
#pragma unroll
        for (int nt = 0; nt < 8; nt++) {
            r0 = fmaxf(r0, fmaxf(accS[nt][0], accS[nt][1]));
            r1 = fmaxf(r1, fmaxf(accS[nt][2], accS[nt][3]));
        }
        r0 = fmaxf(r0, __shfl_xor_sync(0xffffffffu, r0, 1));
        r0 = fmaxf(r0, __shfl_xor_sync(0xffffffffu, r0, 2));
        r1 = fmaxf(r1, __shfl_xor_sync(0xffffffffu, r1, 1));
        r1 = fmaxf(r1, __shfl_xor_sync(0xffffffffu, r1, 2));
        const float mn0 = fmaxf(m0, r0);
        const float mn1 = fmaxf(m1, r1);
        const float al0 = exp2f(m0 - mn0);
        const float al1 = exp2f(m1 - mn1);
        float rs0 = 0.f, rs1 = 0.f;

        // P as A-fragments directly (C-frag of S == A-frag of P identity)
        uint32_t phA[8], phB[8];
#pragma unroll
        for (int nt = 0; nt < 8; nt++) {
            __half2 h01 = __floats2half2_rn(exp2f(accS[nt][0] - mn0),
                                            exp2f(accS[nt][1] - mn0));
            __half2 h23 = __floats2half2_rn(exp2f(accS[nt][2] - mn1),
                                            exp2f(accS[nt][3] - mn1));
            float2 f01 = __half22float2(h01);
            float2 f23 = __half22float2(h23);
            rs0 += f01.x + f01.y;
            rs1 += f23.x + f23.y;
            phA[nt] = *(uint32_t*)&h01;
            phB[nt] = *(uint32_t*)&h23;
        }
        rs0 += __shfl_xor_sync(0xffffffffu, rs0, 1);
        rs0 += __shfl_xor_sync(0xffffffffu, rs0, 2);
        rs1 += __shfl_xor_sync(0xffffffffu, rs1, 1);
        rs1 += __shfl_xor_sync(0xffffffffu, rs1, 2);
        l0 = l0 * al0 + rs0;
        l1 = l1 * al1 + rs1;
        m0 = mn0; m1 = mn1;
#pragma unroll
        for (int nt = 0; nt < 8; nt++) {
            accO[nt][0] *= al0; accO[nt][1] *= al0;
            accO[nt][2] *= al1; accO[nt][3] *= al1;
        }

        // O += P V (P from registers; V: B-frag via ldmatrix.trans)
#pragma unroll
        for (int kk = 0; kk < 4; kk++) {
            uint32_t ap[4];
            ap[0] = phA[2 * kk];
            ap[1] = phB[2 * kk];
            ap[2] = phA[2 * kk + 1];
            ap[3] = phB[2 * kk + 1];
#pragma unroll
            for (int p = 0; p < 4; p++) {
                uint32_t v0, v1, v2, v3;
                ldsm_x4_trans(v0, v1, v2, v3,
                              sVb[buf] + 2u * ((kk * 16 + vj) * FSTR + p * 16 + vd));
                mma_f16(accO[2 * p],     ap, v0, v1);
                mma_f16(accO[2 * p + 1], ap, v2, v3);
            }
        }
        __syncthreads();  // readers done before buf overwritten next iter
    }

    // Epilogue: normalize, write fp16 att [B,T,C]
    const float inv0 = 1.f / l0;
    const float inv1 = 1.f / l1;
    const int r0w = q0 + warp * 16 + g;
    __half* o0 = att + (size_t)b * TSZ * DIM + (size_t)r0w * DIM + hoff;
    __half* o1 = o0 + (size_t)8 * DIM;
#pragma unroll
    for (int nt = 0; nt < 8; nt++) {
        __half2 v0 = __floats2half2_rn(accO[nt][0] * inv0, accO[nt][1] * inv0);
        __half2 v1 = __floats2half2_rn(accO[nt][2] * inv1, accO[nt][3] * inv1);
        *(uint32_t*)&o0[nt * 8 + 2 * t] = *(uint32_t*)&v0;
        *(uint32_t*)&o1[nt * 8 + 2 * t] = *(uint32_t*)&v1;
    }
}

// ---------------------------------------------------------------------------
extern "C" void kernel_launch(void* const* d_in, const int* in_sizes, int n_in,
                              void* d_out, int out_size) {
    const float* x     = (const float*)d_in[0];  // [4,1024,1024]
    const float* Wqkv  = (const float*)d_in[1];  // [3072,1024]
    const float* Wproj = (const float*)d_in[2];  // [1024,1024]
    const float* bproj = (const float*)d_in[3];  // [1024]
    float* out = (float*)d_out;                  // [4,1024,1024]

    __half *xh, *wqkvh, *wprojh, *qkvh, *atth;
    cudaGetSymbolAddress((void**)&xh, g_xh);
    cudaGetSymbolAddress((void**)&wqkvh, g_wqkvh);
    cudaGetSymbolAddress((void**)&wprojh, g_wprojh);
    cudaGetSymbolAddress((void**)&qkvh, g_qkvh);
    cudaGetSymbolAddress((void**)&atth, g_atth);

    cudaFuncSetAttribute(f16_gemm_wide,
                         cudaFuncAttributeMaxDynamicSharedMemorySize, GEMMW_SMEM);
    cudaFuncSetAttribute(f16_gemm_sq,
                         cudaFuncAttributeMaxDynamicSharedMemorySize, GEMMS_SMEM);
    cudaFuncSetAttribute(flash_f16,
                         cudaFuncAttributeMaxDynamicSharedMemorySize, FLASH_SMEM);

    // 0) fused fp32 -> fp16 conversion (x, Wqkv, Wproj)
    cvt3_f32_f16<<<(N_X + N_WQ + N_WP) / 2048, 256>>>(x, Wqkv, Wproj,
                                                      xh, wqkvh, wprojh);

    // 1) QKV projection -> fp16: [4096,1024] x [3072,1024]^T -> [4096,3072]
    f16_gemm_wide<<<dim3(C3 / 256, (BATCH * TSZ) / 128), 512, GEMMW_SMEM>>>(
        xh, wqkvh, qkvh, BATCH * TSZ, C3, DIM);

    // 2) Attention (fp16 in/out, register-resident P)
    flash_f16<<<dim3(TSZ / 128, BATCH * NHEAD), 256, FLASH_SMEM>>>(qkvh, atth);

    // 3) Output projection + bias -> fp32 out
    f16_gemm_sq<<<dim3(DIM / 128, (BATCH * TSZ) / 128), 256, GEMMS_SMEM>>>(
        atth, wprojh, bproj, out, BATCH * TSZ, DIM, DIM);
}